// round 6
// baseline (speedup 1.0000x reference)
#include <cuda_runtime.h>
#include <cuda_bf16.h>
#include <stdint.h>

#define NN 32768      // B*M nodes
#define NH 4
#define DD 64
#define BB 64
#define MM 512
#define EE 524288

// ================= device scratch =================
static __device__ float g_q[NN * 256];
static __device__ float g_k[NN * 256];
static __device__ float g_v[NN * 256];
static __device__ float g_vmean[NN * DD];
static __device__ float g_kv[BB * NH * DD * DD];
static __device__ float g_ksum[BB * NH * DD];
static __device__ float g_vsum[BB * NH * DD];
static __device__ float g_deg[NN];
static __device__ float g_sumsq[2];
static __device__ __align__(16) __nv_bfloat16 g_wth[3 * 256 * 256];  // [w][n][k] = W[k][n] hi
static __device__ __align__(16) __nv_bfloat16 g_wtl[3 * 256 * 256];  // lo residual

// ================= init =================
__global__ void init_kernel() {
    int i = blockIdx.x * 256 + threadIdx.x;
    if (i < NN) g_deg[i] = 0.f;
    if (i < 2) g_sumsq[i] = 0.f;
}

// ================= W transpose + bf16 hi/lo split =================
__global__ void wconv_kernel(const float* __restrict__ Wq, const float* __restrict__ Wk,
                             const float* __restrict__ Wv) {
    int w = blockIdx.y, n = blockIdx.x, k = threadIdx.x;
    const float* W = (w == 0) ? Wq : ((w == 1) ? Wk : Wv);
    float x = W[k * 256 + n];
    __nv_bfloat16 h = __float2bfloat16_rn(x);
    __nv_bfloat16 l = __float2bfloat16_rn(x - __bfloat162float(h));
    g_wth[(w * 256 + n) * 256 + k] = h;
    g_wtl[(w * 256 + n) * 256 + k] = l;
}

// ================= PTX helpers (arch-generic) =================
__device__ __forceinline__ uint32_t smem_u32(const void* p) {
    uint32_t a;
    asm("{ .reg .u64 t; cvta.to.shared.u64 t, %1; cvt.u32.u64 %0, t; }" : "=r"(a) : "l"(p));
    return a;
}
__device__ __forceinline__ void ldmx4(uint32_t* r, uint32_t addr) {
    asm volatile("ldmatrix.sync.aligned.m8n8.x4.shared.b16 {%0,%1,%2,%3}, [%4];"
                 : "=r"(r[0]), "=r"(r[1]), "=r"(r[2]), "=r"(r[3]) : "r"(addr));
}
__device__ __forceinline__ void mma16816(float* d, const uint32_t* a, const uint32_t* b) {
    asm volatile(
        "mma.sync.aligned.m16n8k16.row.col.f32.bf16.bf16.f32 "
        "{%0,%1,%2,%3}, {%4,%5,%6,%7}, {%8,%9}, {%0,%1,%2,%3};"
        : "+f"(d[0]), "+f"(d[1]), "+f"(d[2]), "+f"(d[3])
        : "r"(a[0]), "r"(a[1]), "r"(a[2]), "r"(a[3]), "r"(b[0]), "r"(b[1]));
}
__device__ __forceinline__ void cp16(uint32_t dst, const void* src) {
    asm volatile("cp.async.cg.shared.global [%0], [%1], 16;" :: "r"(dst), "l"(src));
}
#define CP_COMMIT() asm volatile("cp.async.commit_group;" ::: "memory")
#define CP_WAIT0()  asm volatile("cp.async.wait_group 0;" ::: "memory")

// ================= projection GEMM via tensor cores (bf16x3, pipelined) ==========
// grid = (2, 256, 3). CTA tile 128x128, BK=32, 8 warps (2x4), warp tile 64x32.
// Double-buffered dynamic SMEM; A prefetched via regs (converted post-mma),
// B prefetched via cp.async. SROW=40 pad -> conflict-free ldmatrix.
#define SROW 40
#define TILEB (128 * SROW)          // bf16 elems per tile (10240 B)
#define PROJ_SMEM (2 * 4 * TILEB * 2)  // 81920 B

__global__ __launch_bounds__(256, 2) void proj_mma_kernel(
    const float* __restrict__ Xq, const float* __restrict__ Xs,
    const float* __restrict__ bq, const float* __restrict__ bk,
    const float* __restrict__ bv)
{
    extern __shared__ __nv_bfloat16 ps[];

    const int t = threadIdx.x, lane = t & 31, wid = t >> 5;
    const int wm = wid >> 2, wn = wid & 3;
    const int y = blockIdx.z;
    const float* A    = (y == 0) ? Xq : Xs;
    const float* bias = (y == 0) ? bq : ((y == 1) ? bk : bv);
    float* C          = (y == 0) ? g_q : ((y == 1) ? g_k : g_v);
    const int sqidx   = (y == 2) ? -1 : y;
    const int row0 = blockIdx.y * 128;
    const int col0 = blockIdx.x * 128;

    const __nv_bfloat16* Wth = g_wth + y * 65536;
    const __nv_bfloat16* Wtl = g_wtl + y * 65536;

    const uint32_t sbase = smem_u32(ps);
    const uint32_t a_lrow = lane & 15, a_lcol = (lane >> 4) * 8;
    const uint32_t b_lrow = lane & 7,  b_lcol = (lane >> 3) * 8;

    float acc[4][4][4];
#pragma unroll
    for (int i = 0; i < 4; i++)
#pragma unroll
        for (int j = 0; j < 4; j++)
#pragma unroll
            for (int r = 0; r < 4; r++) acc[i][j][r] = 0.f;

    const int ar = t >> 1, ac = (t & 1);

    float4 pa[4];
    // --- helpers as lambdas ---
    auto ldA = [&](int kt) {
        const int k0 = kt * 32;
#pragma unroll
        for (int i = 0; i < 4; i++) {
            int cf = ac * 4 + i;
            pa[i] = *(const float4*)(A + (size_t)(row0 + ar) * 256 + k0 + cf * 4);
        }
    };
    auto stA = [&](int buf) {
        __nv_bfloat16* Ah = ps + buf * 4 * TILEB;
        __nv_bfloat16* Al = Ah + TILEB;
#pragma unroll
        for (int i = 0; i < 4; i++) {
            int cf = ac * 4 + i;
            float4 a4 = pa[i];
            __nv_bfloat16 h0 = __float2bfloat16_rn(a4.x), h1 = __float2bfloat16_rn(a4.y);
            __nv_bfloat16 h2 = __float2bfloat16_rn(a4.z), h3 = __float2bfloat16_rn(a4.w);
            __nv_bfloat16 l0 = __float2bfloat16_rn(a4.x - __bfloat162float(h0));
            __nv_bfloat16 l1 = __float2bfloat16_rn(a4.y - __bfloat162float(h1));
            __nv_bfloat16 l2 = __float2bfloat16_rn(a4.z - __bfloat162float(h2));
            __nv_bfloat16 l3 = __float2bfloat16_rn(a4.w - __bfloat162float(h3));
            __nv_bfloat162 ph0, ph1, pl0, pl1;
            ph0.x = h0; ph0.y = h1; ph1.x = h2; ph1.y = h3;
            pl0.x = l0; pl0.y = l1; pl1.x = l2; pl1.y = l3;
            int o = ar * SROW + cf * 4;
            *(uint2*)&Ah[o] = make_uint2(*(uint32_t*)&ph0, *(uint32_t*)&ph1);
            *(uint2*)&Al[o] = make_uint2(*(uint32_t*)&pl0, *(uint32_t*)&pl1);
        }
    };
    auto cpB = [&](int kt, int buf) {
        const int k0 = kt * 32;
        const int row = t >> 1;
        uint32_t bh_s = sbase + (buf * 4 * TILEB + 2 * TILEB) * 2;
        uint32_t bl_s = bh_s + TILEB * 2;
#pragma unroll
        for (int j = 0; j < 2; j++) {
            int u = (t & 1) * 2 + j;
            uint32_t so = (row * SROW + u * 8) * 2;
            const char* gh = (const char*)(Wth + (size_t)(col0 + row) * 256 + k0) + u * 16;
            const char* gl = (const char*)(Wtl + (size_t)(col0 + row) * 256 + k0) + u * 16;
            cp16(bh_s + so, gh);
            cp16(bl_s + so, gl);
        }
    };

    // ---- prologue: fill buffer 0 ----
    ldA(0);
    cpB(0, 0);
    CP_COMMIT();
    stA(0);
    CP_WAIT0();
    __syncthreads();

    for (int kt = 0; kt < 8; kt++) {
        const int cur = kt & 1;
        if (kt < 7) { ldA(kt + 1); cpB(kt + 1, 1 - cur); CP_COMMIT(); }

        const uint32_t base = sbase + cur * 4 * TILEB * 2;
        const uint32_t ah_b = base, al_b = base + TILEB * 2;
        const uint32_t bh_b = base + 2 * TILEB * 2, bl_b = base + 3 * TILEB * 2;

        uint32_t bhf[4][4], blf[4][4];
#pragma unroll
        for (int nf = 0; nf < 4; nf++) {
            uint32_t n = wn * 32 + nf * 8 + b_lrow;
            uint32_t off = (n * SROW + b_lcol) * 2;
            ldmx4(bhf[nf], bh_b + off);
            ldmx4(blf[nf], bl_b + off);
        }
#pragma unroll
        for (int kf = 0; kf < 2; kf++) {
#pragma unroll
            for (int mf = 0; mf < 4; mf++) {
                uint32_t row = wm * 64 + mf * 16 + a_lrow;
                uint32_t off = (row * SROW + kf * 16 + a_lcol) * 2;
                uint32_t ahf[4], alf[4];
                ldmx4(ahf, ah_b + off);
                ldmx4(alf, al_b + off);
#pragma unroll
                for (int nf = 0; nf < 4; nf++) {
                    mma16816(acc[mf][nf], ahf, &bhf[nf][kf * 2]);
                    mma16816(acc[mf][nf], ahf, &blf[nf][kf * 2]);
                    mma16816(acc[mf][nf], alf, &bhf[nf][kf * 2]);
                }
            }
        }
        if (kt < 7) { stA(1 - cur); CP_WAIT0(); }
        __syncthreads();
    }

    // ---- epilogue: bias + store + global sumsq ----
    float ss = 0.f;
    const int rql = lane >> 2, cql = (lane & 3) * 2;
#pragma unroll
    for (int mf = 0; mf < 4; mf++) {
        int r0 = row0 + wm * 64 + mf * 16 + rql;
#pragma unroll
        for (int nf = 0; nf < 4; nf++) {
            int c = col0 + wn * 32 + nf * 8 + cql;
            float b0 = bias[c], b1 = bias[c + 1];
            float v0 = acc[mf][nf][0] + b0, v1 = acc[mf][nf][1] + b1;
            float v2 = acc[mf][nf][2] + b0, v3 = acc[mf][nf][3] + b1;
            ss += v0 * v0 + v1 * v1 + v2 * v2 + v3 * v3;
            *(float2*)(C + (size_t)r0 * 256 + c)       = make_float2(v0, v1);
            *(float2*)(C + (size_t)(r0 + 8) * 256 + c) = make_float2(v2, v3);
        }
    }
    if (sqidx >= 0) {
#pragma unroll
        for (int o = 16; o > 0; o >>= 1) ss += __shfl_down_sync(0xffffffffu, ss, o);
        if (lane == 0) atomicAdd(&g_sumsq[sqidx], ss);
    }
}

// ================= degree =================
__global__ void deg_kernel(const int* __restrict__ ei) {
    int e = blockIdx.x * 256 + threadIdx.x;
    if (e < EE) atomicAdd(&g_deg[ei[EE + e]], 1.0f);
}

// ================= head-mean of v =================
__global__ void vmean_kernel() {
    int i = blockIdx.x * 256 + threadIdx.x;
    int n = i >> 6, d = i & 63;
    const float* vr = g_v + (size_t)n * 256 + d;
    g_vmean[i] = 0.25f * (vr[0] + vr[64] + vr[128] + vr[192]);
}

// ================= per (b,h): kv, ksum, vsum =================
__global__ __launch_bounds__(256) void kv_kernel() {
    int bh = blockIdx.x;
    int b = bh >> 2, h = bh & 3;
    __shared__ float ks[8][64], vs[8][64];
    int t = threadIdx.x;
    int ty = t >> 4, tx = t & 15;
    float acc[4][4] = {};
    float s1 = 0.f, s2 = 0.f;
    const float* kb = g_k + (size_t)b * 512 * 256 + h * 64;
    const float* vb = g_v + (size_t)b * 512 * 256 + h * 64;

    for (int m0 = 0; m0 < 512; m0 += 8) {
#pragma unroll
        for (int j = 0; j < 2; j++) {
            int i = t + j * 256;
            int r = i >> 6, c2 = i & 63;
            ks[r][c2] = kb[(size_t)(m0 + r) * 256 + c2];
            vs[r][c2] = vb[(size_t)(m0 + r) * 256 + c2];
        }
        __syncthreads();
#pragma unroll
        for (int r = 0; r < 8; r++) {
            float kr[4], vr[4];
            float4 k4 = *(const float4*)&ks[r][ty * 4];
            float4 v4 = *(const float4*)&vs[r][tx * 4];
            kr[0]=k4.x; kr[1]=k4.y; kr[2]=k4.z; kr[3]=k4.w;
            vr[0]=v4.x; vr[1]=v4.y; vr[2]=v4.z; vr[3]=v4.w;
#pragma unroll
            for (int i = 0; i < 4; i++)
#pragma unroll
                for (int j = 0; j < 4; j++)
                    acc[i][j] = fmaf(kr[i], vr[j], acc[i][j]);
        }
        if (t < 64) {
#pragma unroll
            for (int r = 0; r < 8; r++) s1 += ks[r][t];
        } else if (t < 128) {
#pragma unroll
            for (int r = 0; r < 8; r++) s2 += vs[r][t - 64];
        }
        __syncthreads();
    }
    float* kvout = g_kv + (size_t)bh * 4096;
#pragma unroll
    for (int i = 0; i < 4; i++)
#pragma unroll
        for (int j = 0; j < 4; j++)
            kvout[(ty * 4 + i) * 64 + tx * 4 + j] = acc[i][j];
    if (t < 64) g_ksum[bh * 64 + t] = s1;
    else if (t < 128) g_vsum[bh * 64 + (t - 64)] = s2;
}

// ================= fused attention output: P=Q@KV, den, combine -> out ==========
// grid = (64, 8): b, 64-row chunk. All 4 heads in SMEM. Writes final attn term.
// Dynamic SMEM layout (floats):
//   Qs   [4][64][68]  (transposed per head, padded)   offset 0       (17408)
//   KVs  [4][64*64]                                   offset 17408   (16384)
//   ksum [256], vsum [256], den [64*4]                offset 33792
#define ATT_SMEM ((17408 + 16384 + 256 + 256 + 256) * 4)
__global__ __launch_bounds__(256) void att_kernel(const int* __restrict__ nnodes,
                                                  float* __restrict__ out) {
    extern __shared__ float sm[];
    float* Qs   = sm;              // [h][k][m] stride 68
    float* KVs  = sm + 17408;      // [h][k*64+d]
    float* ksum = sm + 33792;
    float* vsum = sm + 34048;
    float* dens = sm + 34304;      // [m][h]

    const int t = threadIdx.x;
    const int b = blockIdx.x, chunk = blockIdx.y;
    const int n0 = b * 512 + chunk * 64;

    // load Q transposed per head
    const float* qb = g_q + (size_t)n0 * 256;
    int la_m = t >> 2, la_k0 = (t & 3) * 4;
#pragma unroll
    for (int h = 0; h < 4; h++) {
        float* Qh = Qs + h * 4352;
#pragma unroll
        for (int j = 0; j < 4; j++) {
            int kk = la_k0 + j * 16;
            float4 v4 = *(const float4*)(qb + (size_t)la_m * 256 + h * 64 + kk);
            Qh[(kk + 0) * 68 + la_m] = v4.x; Qh[(kk + 1) * 68 + la_m] = v4.y;
            Qh[(kk + 2) * 68 + la_m] = v4.z; Qh[(kk + 3) * 68 + la_m] = v4.w;
        }
    }
    // load KV flat (layout matches), ksum, vsum
    const float* kvb = g_kv + (size_t)b * 16384;
#pragma unroll
    for (int j = 0; j < 16; j++)
        *(float4*)&KVs[(t + j * 256) * 4] = *(const float4*)(kvb + (t + j * 256) * 4);
    ksum[t] = g_ksum[b * 256 + t];
    vsum[t] = g_vsum[b * 256 + t];
    __syncthreads();

    // den[m][h] = Q[m,h,:].ksum[h]
    {
        int h = t >> 6, m = t & 63;
        const float* Qh = Qs + h * 4352;
        const float* kh = ksum + h * 64;
        float p = 0.f;
#pragma unroll
        for (int k = 0; k < 64; k++) p = fmaf(Qh[k * 68 + m], kh[k], p);
        dens[m * 4 + h] = p;
    }
    __syncthreads();

    const float s = rsqrtf(g_sumsq[0]) * rsqrtf(g_sumsq[1]);
    const float nnv = (float)nnodes[b];
    const int rm0 = (t >> 4) * 4, cn0 = (t & 15) * 4;

    float o[4][4];
#pragma unroll
    for (int i = 0; i < 4; i++)
#pragma unroll
        for (int j = 0; j < 4; j++) o[i][j] = 0.f;

#pragma unroll
    for (int h = 0; h < 4; h++) {
        const float* Qh = Qs + h * 4352;
        const float* KVh = KVs + h * 4096;
        float acc[4][4] = {};
#pragma unroll
        for (int k = 0; k < 64; k++) {
            float a[4], bb[4];
            float4 t0 = *(const float4*)&Qh[k * 68 + rm0];
            float4 t1 = *(const float4*)&KVh[k * 64 + cn0];
            a[0]=t0.x; a[1]=t0.y; a[2]=t0.z; a[3]=t0.w;
            bb[0]=t1.x; bb[1]=t1.y; bb[2]=t1.z; bb[3]=t1.w;
#pragma unroll
            for (int i = 0; i < 4; i++)
#pragma unroll
                for (int j = 0; j < 4; j++)
                    acc[i][j] = fmaf(a[i], bb[j], acc[i][j]);
        }
#pragma unroll
        for (int i = 0; i < 4; i++) {
            float inv = 1.0f / fmaf(s, dens[(rm0 + i) * 4 + h], nnv);
#pragma unroll
            for (int j = 0; j < 4; j++)
                o[i][j] += fmaf(s, acc[i][j], vsum[h * 64 + cn0 + j]) * inv;
        }
    }
#pragma unroll
    for (int i = 0; i < 4; i++)
        *(float4*)(out + (size_t)(n0 + rm0 + i) * 64 + cn0) =
            make_float4(0.25f * o[i][0], 0.25f * o[i][1], 0.25f * o[i][2], 0.25f * o[i][3]);
}

// ================= GCN scatter =================
__global__ void gcn_kernel(const int* __restrict__ ei, const float* __restrict__ ew,
                           float* __restrict__ out) {
    int gid = blockIdx.x * 256 + threadIdx.x;
    int e = gid >> 4, li = gid & 15;
    int row = ei[e];
    int col = ei[EE + e];
    float p = g_deg[col] * g_deg[row];
    float coeff = (p > 0.f) ? ew[e] * rsqrtf(p) : 0.f;
    float4 vv = *(const float4*)(g_vmean + (size_t)row * 64 + li * 4);
    float* dst = out + (size_t)col * 64 + li * 4;
    asm volatile("red.global.add.v4.f32 [%0], {%1,%2,%3,%4};"
                 :: "l"(dst), "f"(coeff * vv.x), "f"(coeff * vv.y),
                    "f"(coeff * vv.z), "f"(coeff * vv.w)
                 : "memory");
}

extern "C" void kernel_launch(void* const* d_in, const int* in_sizes, int n_in,
                              void* d_out, int out_size) {
    const float* Xq = (const float*)d_in[0];
    const float* Xs = (const float*)d_in[1];
    const float* ew = (const float*)d_in[2];
    const float* Wq = (const float*)d_in[3];
    const float* bq = (const float*)d_in[4];
    const float* Wk = (const float*)d_in[5];
    const float* bk = (const float*)d_in[6];
    const float* Wv = (const float*)d_in[7];
    const float* bv = (const float*)d_in[8];
    const int*   nn = (const int*)d_in[9];
    const int*   ei = (const int*)d_in[10];
    float* out = (float*)d_out;

    cudaFuncSetAttribute(proj_mma_kernel, cudaFuncAttributeMaxDynamicSharedMemorySize, PROJ_SMEM);
    cudaFuncSetAttribute(att_kernel, cudaFuncAttributeMaxDynamicSharedMemorySize, ATT_SMEM);

    init_kernel<<<128, 256>>>();
    wconv_kernel<<<dim3(256, 3), 256>>>(Wq, Wk, Wv);
    proj_mma_kernel<<<dim3(2, 256, 3), 256, PROJ_SMEM>>>(Xq, Xs, bq, bk, bv);
    deg_kernel<<<EE / 256, 256>>>(ei);
    vmean_kernel<<<(NN * 64) / 256, 256>>>();
    kv_kernel<<<BB * NH, 256>>>();
    att_kernel<<<dim3(BB, 8), 256, ATT_SMEM>>>(nn, out);
    gcn_kernel<<<(EE * 16) / 256, 256>>>(ei, ew, out);
}

// round 7
// speedup vs baseline: 1.4744x; 1.4744x over previous
#include <cuda_runtime.h>
#include <cuda_bf16.h>
#include <stdint.h>

#define NN 32768      // B*M nodes
#define NH 4
#define DD 64
#define BB 64
#define MM 512
#define EE 524288

// ================= device scratch =================
static __device__ float g_q[NN * 256];
static __device__ float g_k[NN * 256];
static __device__ float g_v[NN * 256];
static __device__ float g_vmean[NN * DD];
static __device__ float g_kv[BB * NH * DD * DD];
static __device__ float g_ksum[BB * NH * DD];
static __device__ float g_vsum[BB * NH * DD];
static __device__ float g_deg[NN];
static __device__ float g_sumsq[2];
static __device__ __align__(16) __nv_bfloat16 g_wth[3 * 256 * 256];  // [w][n][k] = W[k][n] hi
static __device__ __align__(16) __nv_bfloat16 g_wtl[3 * 256 * 256];  // lo residual

// ================= init =================
__global__ void init_kernel() {
    int i = blockIdx.x * 256 + threadIdx.x;
    if (i < NN) g_deg[i] = 0.f;
    if (i < 2) g_sumsq[i] = 0.f;
}

// ================= W transpose + bf16 hi/lo split =================
__global__ void wconv_kernel(const float* __restrict__ Wq, const float* __restrict__ Wk,
                             const float* __restrict__ Wv) {
    int w = blockIdx.y, n = blockIdx.x, k = threadIdx.x;
    const float* W = (w == 0) ? Wq : ((w == 1) ? Wk : Wv);
    float x = W[k * 256 + n];
    __nv_bfloat16 h = __float2bfloat16_rn(x);
    __nv_bfloat16 l = __float2bfloat16_rn(x - __bfloat162float(h));
    g_wth[(w * 256 + n) * 256 + k] = h;
    g_wtl[(w * 256 + n) * 256 + k] = l;
}

// ================= mma.sync helpers (arch-generic PTX) =================
__device__ __forceinline__ uint32_t smem_u32(const void* p) {
    uint32_t a;
    asm("{ .reg .u64 t; cvta.to.shared.u64 t, %1; cvt.u32.u64 %0, t; }" : "=r"(a) : "l"(p));
    return a;
}
__device__ __forceinline__ void ldmx4(uint32_t* r, uint32_t addr) {
    asm volatile("ldmatrix.sync.aligned.m8n8.x4.shared.b16 {%0,%1,%2,%3}, [%4];"
                 : "=r"(r[0]), "=r"(r[1]), "=r"(r[2]), "=r"(r[3]) : "r"(addr));
}
__device__ __forceinline__ void mma16816(float* d, const uint32_t* a, const uint32_t* b) {
    asm volatile(
        "mma.sync.aligned.m16n8k16.row.col.f32.bf16.bf16.f32 "
        "{%0,%1,%2,%3}, {%4,%5,%6,%7}, {%8,%9}, {%0,%1,%2,%3};"
        : "+f"(d[0]), "+f"(d[1]), "+f"(d[2]), "+f"(d[3])
        : "r"(a[0]), "r"(a[1]), "r"(a[2]), "r"(a[3]), "r"(b[0]), "r"(b[1]));
}

// ================= projection GEMM via tensor cores (bf16x3 split) =================
// EXACT R4 configuration (known good): grid (2, 256, 3), CTA tile 128x128, BK=32,
// 8 warps (2x4), warp tile 64x32, static SMEM, SROW=40 pad.
#define SROW 40
__global__ __launch_bounds__(256, 2) void proj_mma_kernel(
    const float* __restrict__ Xq, const float* __restrict__ Xs,
    const float* __restrict__ bq, const float* __restrict__ bk,
    const float* __restrict__ bv)
{
    __shared__ __nv_bfloat16 Ah[128 * SROW], Al[128 * SROW];
    __shared__ __nv_bfloat16 Bh[128 * SROW], Bl[128 * SROW];

    const int t = threadIdx.x, lane = t & 31, wid = t >> 5;
    const int wm = wid >> 2, wn = wid & 3;          // 2 x 4 warp grid
    const int y = blockIdx.z;
    const float* A    = (y == 0) ? Xq : Xs;
    const float* bias = (y == 0) ? bq : ((y == 1) ? bk : bv);
    float* C          = (y == 0) ? g_q : ((y == 1) ? g_k : g_v);
    const int sqidx   = (y == 2) ? -1 : y;
    const int row0 = blockIdx.y * 128;
    const int col0 = blockIdx.x * 128;

    const __nv_bfloat16* Wth = g_wth + y * 65536;
    const __nv_bfloat16* Wtl = g_wtl + y * 65536;

    const uint32_t ah_b = smem_u32(Ah), al_b = smem_u32(Al);
    const uint32_t bh_b = smem_u32(Bh), bl_b = smem_u32(Bl);

    const uint32_t a_lrow = lane & 15, a_lcol = (lane >> 4) * 8;
    const uint32_t b_lrow = lane & 7, b_lcol = (lane >> 3) * 8;

    float acc[4][4][4];
#pragma unroll
    for (int i = 0; i < 4; i++)
#pragma unroll
        for (int j = 0; j < 4; j++)
#pragma unroll
            for (int r = 0; r < 4; r++) acc[i][j][r] = 0.f;

    const int ar = t >> 1, ac = (t & 1);       // A loader: 2 threads/row
    const int br2 = t >> 1, bq2 = t & 1;       // B loader

    for (int kt = 0; kt < 8; kt++) {
        const int k0 = kt * 32;
        __syncthreads();
        // ---- A chunk: fp32 -> bf16 hi/lo ----
#pragma unroll
        for (int i = 0; i < 4; i++) {
            int cf = ac * 4 + i;               // float4 index 0..7
            float4 a4 = *(const float4*)(A + (size_t)(row0 + ar) * 256 + k0 + cf * 4);
            __nv_bfloat16 h0 = __float2bfloat16_rn(a4.x), h1 = __float2bfloat16_rn(a4.y);
            __nv_bfloat16 h2 = __float2bfloat16_rn(a4.z), h3 = __float2bfloat16_rn(a4.w);
            __nv_bfloat16 l0 = __float2bfloat16_rn(a4.x - __bfloat162float(h0));
            __nv_bfloat16 l1 = __float2bfloat16_rn(a4.y - __bfloat162float(h1));
            __nv_bfloat16 l2 = __float2bfloat16_rn(a4.z - __bfloat162float(h2));
            __nv_bfloat16 l3 = __float2bfloat16_rn(a4.w - __bfloat162float(h3));
            __nv_bfloat162 ph0, ph1, pl0, pl1;
            ph0.x = h0; ph0.y = h1; ph1.x = h2; ph1.y = h3;
            pl0.x = l0; pl0.y = l1; pl1.x = l2; pl1.y = l3;
            int o = ar * SROW + cf * 4;
            *(uint2*)&Ah[o] = make_uint2(*(uint32_t*)&ph0, *(uint32_t*)&ph1);
            *(uint2*)&Al[o] = make_uint2(*(uint32_t*)&pl0, *(uint32_t*)&pl1);
        }
        // ---- B chunk (pre-split bf16 W^T rows) ----
#pragma unroll
        for (int j = 0; j < 2; j++) {
            int u = bq2 * 2 + j;               // uint4 index 0..3 (8 bf16 each)
            const char* srch = (const char*)(Wth + (size_t)(col0 + br2) * 256 + k0) + u * 16;
            const char* srcl = (const char*)(Wtl + (size_t)(col0 + br2) * 256 + k0) + u * 16;
            int o = br2 * SROW + u * 8;
            *(uint4*)&Bh[o] = *(const uint4*)srch;
            *(uint4*)&Bl[o] = *(const uint4*)srcl;
        }
        __syncthreads();

        // ---- preload B fragments (both k-halves) ----
        uint32_t bhf[4][4], blf[4][4];
#pragma unroll
        for (int nf = 0; nf < 4; nf++) {
            uint32_t n = wn * 32 + nf * 8 + b_lrow;
            uint32_t off = (n * SROW + b_lcol) * 2;
            ldmx4(bhf[nf], bh_b + off);
            ldmx4(blf[nf], bl_b + off);
        }
        // ---- mma ----
#pragma unroll
        for (int kf = 0; kf < 2; kf++) {
#pragma unroll
            for (int mf = 0; mf < 4; mf++) {
                uint32_t row = wm * 64 + mf * 16 + a_lrow;
                uint32_t off = (row * SROW + kf * 16 + a_lcol) * 2;
                uint32_t ahf[4], alf[4];
                ldmx4(ahf, ah_b + off);
                ldmx4(alf, al_b + off);
#pragma unroll
                for (int nf = 0; nf < 4; nf++) {
                    mma16816(acc[mf][nf], ahf, &bhf[nf][kf * 2]);
                    mma16816(acc[mf][nf], ahf, &blf[nf][kf * 2]);
                    mma16816(acc[mf][nf], alf, &bhf[nf][kf * 2]);
                }
            }
        }
    }

    // ---- epilogue: bias + store + global sumsq ----
    float ss = 0.f;
    const int rql = lane >> 2, cql = (lane & 3) * 2;
#pragma unroll
    for (int mf = 0; mf < 4; mf++) {
        int r0 = row0 + wm * 64 + mf * 16 + rql;
#pragma unroll
        for (int nf = 0; nf < 4; nf++) {
            int c = col0 + wn * 32 + nf * 8 + cql;
            float b0 = bias[c], b1 = bias[c + 1];
            float v0 = acc[mf][nf][0] + b0, v1 = acc[mf][nf][1] + b1;
            float v2 = acc[mf][nf][2] + b0, v3 = acc[mf][nf][3] + b1;
            ss += v0 * v0 + v1 * v1 + v2 * v2 + v3 * v3;
            *(float2*)(C + (size_t)r0 * 256 + c)       = make_float2(v0, v1);
            *(float2*)(C + (size_t)(r0 + 8) * 256 + c) = make_float2(v2, v3);
        }
    }
    if (sqidx >= 0) {
#pragma unroll
        for (int o = 16; o > 0; o >>= 1) ss += __shfl_down_sync(0xffffffffu, ss, o);
        if (lane == 0) atomicAdd(&g_sumsq[sqidx], ss);
    }
}

// ================= degree =================
__global__ void deg_kernel(const int* __restrict__ ei) {
    int e = blockIdx.x * 256 + threadIdx.x;
    if (e < EE) atomicAdd(&g_deg[ei[EE + e]], 1.0f);
}

// ================= head-mean of v =================
__global__ void vmean_kernel() {
    int i = blockIdx.x * 256 + threadIdx.x;
    int n = i >> 6, d = i & 63;
    const float* vr = g_v + (size_t)n * 256 + d;
    g_vmean[i] = 0.25f * (vr[0] + vr[64] + vr[128] + vr[192]);
}

// ================= per (b,h): kv, ksum, vsum =================
__global__ __launch_bounds__(256) void kv_kernel() {
    int bh = blockIdx.x;
    int b = bh >> 2, h = bh & 3;
    __shared__ float ks[8][64], vs[8][64];
    int t = threadIdx.x;
    int ty = t >> 4, tx = t & 15;
    float acc[4][4] = {};
    float s1 = 0.f, s2 = 0.f;
    const float* kb = g_k + (size_t)b * 512 * 256 + h * 64;
    const float* vb = g_v + (size_t)b * 512 * 256 + h * 64;

    for (int m0 = 0; m0 < 512; m0 += 8) {
#pragma unroll
        for (int j = 0; j < 2; j++) {
            int i = t + j * 256;
            int r = i >> 6, c2 = i & 63;
            ks[r][c2] = kb[(size_t)(m0 + r) * 256 + c2];
            vs[r][c2] = vb[(size_t)(m0 + r) * 256 + c2];
        }
        __syncthreads();
#pragma unroll
        for (int r = 0; r < 8; r++) {
            float kr[4], vr[4];
            float4 k4 = *(const float4*)&ks[r][ty * 4];
            float4 v4 = *(const float4*)&vs[r][tx * 4];
            kr[0]=k4.x; kr[1]=k4.y; kr[2]=k4.z; kr[3]=k4.w;
            vr[0]=v4.x; vr[1]=v4.y; vr[2]=v4.z; vr[3]=v4.w;
#pragma unroll
            for (int i = 0; i < 4; i++)
#pragma unroll
                for (int j = 0; j < 4; j++)
                    acc[i][j] = fmaf(kr[i], vr[j], acc[i][j]);
        }
        if (t < 64) {
#pragma unroll
            for (int r = 0; r < 8; r++) s1 += ks[r][t];
        } else if (t < 128) {
#pragma unroll
            for (int r = 0; r < 8; r++) s2 += vs[r][t - 64];
        }
        __syncthreads();
    }
    float* kvout = g_kv + (size_t)bh * 4096;
#pragma unroll
    for (int i = 0; i < 4; i++)
#pragma unroll
        for (int j = 0; j < 4; j++)
            kvout[(ty * 4 + i) * 64 + tx * 4 + j] = acc[i][j];
    if (t < 64) g_ksum[bh * 64 + t] = s1;
    else if (t < 128) g_vsum[bh * 64 + (t - 64)] = s2;
}

// ================= fused attention output: P=Q@KV, den, combine -> out ==========
// grid = (64, 16): b, 32-row chunk. All 4 heads in SMEM. 105KB -> 2 CTAs/SM.
// SMEM floats: Qs [4][64][36] = 9216 | KVs [4][4096] = 16384 | ksum 256 | vsum 256 | dens 128
#define QS_STRIDE 36
#define ATT_FLOATS (9216 + 16384 + 256 + 256 + 128)
#define ATT_SMEM (ATT_FLOATS * 4)
__global__ __launch_bounds__(256, 2) void att_kernel(const int* __restrict__ nnodes,
                                                     float* __restrict__ out) {
    extern __shared__ float sm[];
    float* Qs   = sm;                    // [h][k][m] stride QS_STRIDE
    float* KVs  = sm + 9216;             // [h][k*64+d]
    float* ksum = sm + 9216 + 16384;
    float* vsum = ksum + 256;
    float* dens = vsum + 256;            // [m][h], m in 0..31

    const int t = threadIdx.x;
    const int b = blockIdx.x, chunk = blockIdx.y;
    const int n0 = b * 512 + chunk * 32;

    // load Q (32 rows x 256 cols) transposed per head: 8 threads/row, 8 float4 each
    {
        const float* qb = g_q + (size_t)n0 * 256;
        int la_m = t >> 3;                     // 0..31
        int cb0 = (t & 7) * 4;                 // starting col within a 32-col stripe
#pragma unroll
        for (int j = 0; j < 8; j++) {
            int c = cb0 + j * 32;              // global col 0..255
            int h = c >> 6, kk = c & 63;
            float4 v4 = *(const float4*)(qb + (size_t)la_m * 256 + c);
            float* Qh = Qs + h * (64 * QS_STRIDE);
            Qh[(kk + 0) * QS_STRIDE + la_m] = v4.x;
            Qh[(kk + 1) * QS_STRIDE + la_m] = v4.y;
            Qh[(kk + 2) * QS_STRIDE + la_m] = v4.z;
            Qh[(kk + 3) * QS_STRIDE + la_m] = v4.w;
        }
    }
    // load KV flat, ksum, vsum
    {
        const float* kvb = g_kv + (size_t)b * 16384;
#pragma unroll
        for (int j = 0; j < 16; j++)
            *(float4*)&KVs[(t + j * 256) * 4] = *(const float4*)(kvb + (t + j * 256) * 4);
        ksum[t] = g_ksum[b * 256 + t];
        vsum[t] = g_vsum[b * 256 + t];
    }
    __syncthreads();

    // den[m][h] = Q[m,h,:].ksum[h]   (128 threads active)
    if (t < 128) {
        int h = t >> 5, m = t & 31;
        const float* Qh = Qs + h * (64 * QS_STRIDE);
        const float* kh = ksum + h * 64;
        float p = 0.f;
#pragma unroll
        for (int k = 0; k < 64; k++) p = fmaf(Qh[k * QS_STRIDE + m], kh[k], p);
        dens[m * 4 + h] = p;
    }
    __syncthreads();

    const float s = rsqrtf(g_sumsq[0]) * rsqrtf(g_sumsq[1]);
    const float nnv = (float)nnodes[b];
    const int rm0 = (t >> 4) * 2, cn0 = (t & 15) * 4;   // 2 rows x 4 cols per thread

    float o[2][4];
#pragma unroll
    for (int i = 0; i < 2; i++)
#pragma unroll
        for (int j = 0; j < 4; j++) o[i][j] = 0.f;

#pragma unroll
    for (int h = 0; h < 4; h++) {
        const float* Qh = Qs + h * (64 * QS_STRIDE);
        const float* KVh = KVs + h * 4096;
        float acc[2][4] = {};
#pragma unroll
        for (int k = 0; k < 64; k++) {
            float2 qa = *(const float2*)&Qh[k * QS_STRIDE + rm0];
            float4 t1 = *(const float4*)&KVh[k * 64 + cn0];
            acc[0][0] = fmaf(qa.x, t1.x, acc[0][0]);
            acc[0][1] = fmaf(qa.x, t1.y, acc[0][1]);
            acc[0][2] = fmaf(qa.x, t1.z, acc[0][2]);
            acc[0][3] = fmaf(qa.x, t1.w, acc[0][3]);
            acc[1][0] = fmaf(qa.y, t1.x, acc[1][0]);
            acc[1][1] = fmaf(qa.y, t1.y, acc[1][1]);
            acc[1][2] = fmaf(qa.y, t1.z, acc[1][2]);
            acc[1][3] = fmaf(qa.y, t1.w, acc[1][3]);
        }
#pragma unroll
        for (int i = 0; i < 2; i++) {
            float inv = 1.0f / fmaf(s, dens[(rm0 + i) * 4 + h], nnv);
#pragma unroll
            for (int j = 0; j < 4; j++)
                o[i][j] += fmaf(s, acc[i][j], vsum[h * 64 + cn0 + j]) * inv;
        }
    }
#pragma unroll
    for (int i = 0; i < 2; i++)
        *(float4*)(out + (size_t)(n0 + rm0 + i) * 64 + cn0) =
            make_float4(0.25f * o[i][0], 0.25f * o[i][1], 0.25f * o[i][2], 0.25f * o[i][3]);
}

// ================= GCN scatter =================
__global__ void gcn_kernel(const int* __restrict__ ei, const float* __restrict__ ew,
                           float* __restrict__ out) {
    int gid = blockIdx.x * 256 + threadIdx.x;
    int e = gid >> 4, li = gid & 15;
    int row = ei[e];
    int col = ei[EE + e];
    float p = g_deg[col] * g_deg[row];
    float coeff = (p > 0.f) ? ew[e] * rsqrtf(p) : 0.f;
    float4 vv = *(const float4*)(g_vmean + (size_t)row * 64 + li * 4);
    float* dst = out + (size_t)col * 64 + li * 4;
    asm volatile("red.global.add.v4.f32 [%0], {%1,%2,%3,%4};"
                 :: "l"(dst), "f"(coeff * vv.x), "f"(coeff * vv.y),
                    "f"(coeff * vv.z), "f"(coeff * vv.w)
                 : "memory");
}

extern "C" void kernel_launch(void* const* d_in, const int* in_sizes, int n_in,
                              void* d_out, int out_size) {
    const float* Xq = (const float*)d_in[0];
    const float* Xs = (const float*)d_in[1];
    const float* ew = (const float*)d_in[2];
    const float* Wq = (const float*)d_in[3];
    const float* bq = (const float*)d_in[4];
    const float* Wk = (const float*)d_in[5];
    const float* bk = (const float*)d_in[6];
    const float* Wv = (const float*)d_in[7];
    const float* bv = (const float*)d_in[8];
    const int*   nn = (const int*)d_in[9];
    const int*   ei = (const int*)d_in[10];
    float* out = (float*)d_out;

    cudaFuncSetAttribute(att_kernel, cudaFuncAttributeMaxDynamicSharedMemorySize, ATT_SMEM);

    init_kernel<<<128, 256>>>();
    wconv_kernel<<<dim3(256, 3), 256>>>(Wq, Wk, Wv);
    proj_mma_kernel<<<dim3(2, 256, 3), 256>>>(Xq, Xs, bq, bk, bv);
    deg_kernel<<<EE / 256, 256>>>(ei);
    vmean_kernel<<<(NN * 64) / 256, 256>>>();
    kv_kernel<<<BB * NH, 256>>>();
    att_kernel<<<dim3(BB, 16), 256, ATT_SMEM>>>(nn, out);
    gcn_kernel<<<(EE * 16) / 256, 256>>>(ei, ew, out);
}

// round 8
// speedup vs baseline: 1.5706x; 1.0653x over previous
#include <cuda_runtime.h>
#include <cuda_fp16.h>
#include <stdint.h>

#define NN 32768      // B*M nodes
#define NH 4
#define DD 64
#define BB 64
#define MM 512
#define EE 524288

// ================= device scratch =================
static __device__ float g_q[NN * 256];
static __device__ float g_k[NN * 256];
static __device__ float g_v[NN * 256];
static __device__ float g_vmean[NN * DD];
static __device__ float g_kv[BB * NH * DD * DD];
static __device__ float g_ksum[BB * NH * DD];
static __device__ float g_vsum[BB * NH * DD];
static __device__ float g_deg[NN];
static __device__ float g_sumsq[2];
static __device__ __align__(16) __half g_wth[3 * 256 * 256];  // [w][n][k] = W[k][n] hi
static __device__ __align__(16) __half g_wtl[3 * 256 * 256];  // lo residual

// ================= init =================
__global__ void init_kernel() {
    int i = blockIdx.x * 256 + threadIdx.x;
    if (i < NN) g_deg[i] = 0.f;
    if (i < 2) g_sumsq[i] = 0.f;
}

// ================= W transpose + fp16 hi/lo split =================
__global__ void wconv_kernel(const float* __restrict__ Wq, const float* __restrict__ Wk,
                             const float* __restrict__ Wv) {
    int w = blockIdx.y, n = blockIdx.x, k = threadIdx.x;
    const float* W = (w == 0) ? Wq : ((w == 1) ? Wk : Wv);
    float x = W[k * 256 + n];
    __half h = __float2half_rn(x);
    __half l = __float2half_rn(x - __half2float(h));
    g_wth[(w * 256 + n) * 256 + k] = h;
    g_wtl[(w * 256 + n) * 256 + k] = l;
}

// ================= mma.sync helpers (arch-generic PTX) =================
__device__ __forceinline__ uint32_t smem_u32(const void* p) {
    uint32_t a;
    asm("{ .reg .u64 t; cvta.to.shared.u64 t, %1; cvt.u32.u64 %0, t; }" : "=r"(a) : "l"(p));
    return a;
}
__device__ __forceinline__ void ldmx4(uint32_t* r, uint32_t addr) {
    asm volatile("ldmatrix.sync.aligned.m8n8.x4.shared.b16 {%0,%1,%2,%3}, [%4];"
                 : "=r"(r[0]), "=r"(r[1]), "=r"(r[2]), "=r"(r[3]) : "r"(addr));
}
__device__ __forceinline__ void mma16816(float* d, const uint32_t* a, const uint32_t* b) {
    asm volatile(
        "mma.sync.aligned.m16n8k16.row.col.f32.f16.f16.f32 "
        "{%0,%1,%2,%3}, {%4,%5,%6,%7}, {%8,%9}, {%0,%1,%2,%3};"
        : "+f"(d[0]), "+f"(d[1]), "+f"(d[2]), "+f"(d[3])
        : "r"(a[0]), "r"(a[1]), "r"(a[2]), "r"(a[3]), "r"(b[0]), "r"(b[1]));
}

// ================= projection GEMM via tensor cores (fp16 2-term) =================
// D = Ah*Wh + Ah*Wl  (A rounded to fp16 once; W pre-split hi/lo to 2^-22).
// grid (2, 256, 3), CTA tile 128x128, BK=32, 8 warps (2x4), warp tile 64x32.
#define SROW 40
__global__ __launch_bounds__(256, 2) void proj_mma_kernel(
    const float* __restrict__ Xq, const float* __restrict__ Xs,
    const float* __restrict__ bq, const float* __restrict__ bk,
    const float* __restrict__ bv)
{
    __shared__ __half Ah[128 * SROW];
    __shared__ __half Bh[128 * SROW], Bl[128 * SROW];

    const int t = threadIdx.x, lane = t & 31, wid = t >> 5;
    const int wm = wid >> 2, wn = wid & 3;          // 2 x 4 warp grid
    const int y = blockIdx.z;
    const float* A    = (y == 0) ? Xq : Xs;
    const float* bias = (y == 0) ? bq : ((y == 1) ? bk : bv);
    float* C          = (y == 0) ? g_q : ((y == 1) ? g_k : g_v);
    const int sqidx   = (y == 2) ? -1 : y;
    const int row0 = blockIdx.y * 128;
    const int col0 = blockIdx.x * 128;

    const __half* Wth = g_wth + y * 65536;
    const __half* Wtl = g_wtl + y * 65536;

    const uint32_t ah_b = smem_u32(Ah);
    const uint32_t bh_b = smem_u32(Bh), bl_b = smem_u32(Bl);

    const uint32_t a_lrow = lane & 15, a_lcol = (lane >> 4) * 8;
    const uint32_t b_lrow = lane & 7, b_lcol = (lane >> 3) * 8;

    float acc[4][4][4];
#pragma unroll
    for (int i = 0; i < 4; i++)
#pragma unroll
        for (int j = 0; j < 4; j++)
#pragma unroll
            for (int r = 0; r < 4; r++) acc[i][j][r] = 0.f;

    const int ar = t >> 1, ac = (t & 1);       // A loader: 2 threads/row
    const int br2 = t >> 1, bq2 = t & 1;       // B loader

    for (int kt = 0; kt < 8; kt++) {
        const int k0 = kt * 32;
        __syncthreads();
        // ---- A chunk: fp32 -> fp16 (hi only) ----
#pragma unroll
        for (int i = 0; i < 4; i++) {
            int cf = ac * 4 + i;               // float4 index 0..7
            float4 a4 = *(const float4*)(A + (size_t)(row0 + ar) * 256 + k0 + cf * 4);
            __half2 p0 = __floats2half2_rn(a4.x, a4.y);
            __half2 p1 = __floats2half2_rn(a4.z, a4.w);
            int o = ar * SROW + cf * 4;
            *(uint2*)&Ah[o] = make_uint2(*(uint32_t*)&p0, *(uint32_t*)&p1);
        }
        // ---- B chunks (pre-split fp16 W^T rows) ----
#pragma unroll
        for (int j = 0; j < 2; j++) {
            int u = bq2 * 2 + j;               // uint4 index 0..3 (8 halfs each)
            const char* srch = (const char*)(Wth + (size_t)(col0 + br2) * 256 + k0) + u * 16;
            const char* srcl = (const char*)(Wtl + (size_t)(col0 + br2) * 256 + k0) + u * 16;
            int o = br2 * SROW + u * 8;
            *(uint4*)&Bh[o] = *(const uint4*)srch;
            *(uint4*)&Bl[o] = *(const uint4*)srcl;
        }
        __syncthreads();

        // ---- preload B fragments (both k-halves) ----
        uint32_t bhf[4][4], blf[4][4];
#pragma unroll
        for (int nf = 0; nf < 4; nf++) {
            uint32_t n = wn * 32 + nf * 8 + b_lrow;
            uint32_t off = (n * SROW + b_lcol) * 2;
            ldmx4(bhf[nf], bh_b + off);
            ldmx4(blf[nf], bl_b + off);
        }
        // ---- mma: 2 products per fragment ----
#pragma unroll
        for (int kf = 0; kf < 2; kf++) {
#pragma unroll
            for (int mf = 0; mf < 4; mf++) {
                uint32_t row = wm * 64 + mf * 16 + a_lrow;
                uint32_t off = (row * SROW + kf * 16 + a_lcol) * 2;
                uint32_t ahf[4];
                ldmx4(ahf, ah_b + off);
#pragma unroll
                for (int nf = 0; nf < 4; nf++) {
                    mma16816(acc[mf][nf], ahf, &bhf[nf][kf * 2]);
                    mma16816(acc[mf][nf], ahf, &blf[nf][kf * 2]);
                }
            }
        }
    }

    // ---- epilogue: bias + store + global sumsq ----
    float ss = 0.f;
    const int rql = lane >> 2, cql = (lane & 3) * 2;
#pragma unroll
    for (int mf = 0; mf < 4; mf++) {
        int r0 = row0 + wm * 64 + mf * 16 + rql;
#pragma unroll
        for (int nf = 0; nf < 4; nf++) {
            int c = col0 + wn * 32 + nf * 8 + cql;
            float b0 = bias[c], b1 = bias[c + 1];
            float v0 = acc[mf][nf][0] + b0, v1 = acc[mf][nf][1] + b1;
            float v2 = acc[mf][nf][2] + b0, v3 = acc[mf][nf][3] + b1;
            ss += v0 * v0 + v1 * v1 + v2 * v2 + v3 * v3;
            *(float2*)(C + (size_t)r0 * 256 + c)       = make_float2(v0, v1);
            *(float2*)(C + (size_t)(r0 + 8) * 256 + c) = make_float2(v2, v3);
        }
    }
    if (sqidx >= 0) {
#pragma unroll
        for (int o = 16; o > 0; o >>= 1) ss += __shfl_down_sync(0xffffffffu, ss, o);
        if (lane == 0) atomicAdd(&g_sumsq[sqidx], ss);
    }
}

// ================= degree =================
__global__ void deg_kernel(const int* __restrict__ ei) {
    int e = blockIdx.x * 256 + threadIdx.x;
    if (e < EE) atomicAdd(&g_deg[ei[EE + e]], 1.0f);
}

// ================= head-mean of v =================
__global__ void vmean_kernel() {
    int i = blockIdx.x * 256 + threadIdx.x;
    int n = i >> 6, d = i & 63;
    const float* vr = g_v + (size_t)n * 256 + d;
    g_vmean[i] = 0.25f * (vr[0] + vr[64] + vr[128] + vr[192]);
}

// ================= per (b,h): kv, ksum, vsum =================
__global__ __launch_bounds__(256) void kv_kernel() {
    int bh = blockIdx.x;
    int b = bh >> 2, h = bh & 3;
    __shared__ float ks[8][64], vs[8][64];
    int t = threadIdx.x;
    int ty = t >> 4, tx = t & 15;
    float acc[4][4] = {};
    float s1 = 0.f, s2 = 0.f;
    const float* kb = g_k + (size_t)b * 512 * 256 + h * 64;
    const float* vb = g_v + (size_t)b * 512 * 256 + h * 64;

    for (int m0 = 0; m0 < 512; m0 += 8) {
#pragma unroll
        for (int j = 0; j < 2; j++) {
            int i = t + j * 256;
            int r = i >> 6, c2 = i & 63;
            ks[r][c2] = kb[(size_t)(m0 + r) * 256 + c2];
            vs[r][c2] = vb[(size_t)(m0 + r) * 256 + c2];
        }
        __syncthreads();
#pragma unroll
        for (int r = 0; r < 8; r++) {
            float kr[4], vr[4];
            float4 k4 = *(const float4*)&ks[r][ty * 4];
            float4 v4 = *(const float4*)&vs[r][tx * 4];
            kr[0]=k4.x; kr[1]=k4.y; kr[2]=k4.z; kr[3]=k4.w;
            vr[0]=v4.x; vr[1]=v4.y; vr[2]=v4.z; vr[3]=v4.w;
#pragma unroll
            for (int i = 0; i < 4; i++)
#pragma unroll
                for (int j = 0; j < 4; j++)
                    acc[i][j] = fmaf(kr[i], vr[j], acc[i][j]);
        }
        if (t < 64) {
#pragma unroll
            for (int r = 0; r < 8; r++) s1 += ks[r][t];
        } else if (t < 128) {
#pragma unroll
            for (int r = 0; r < 8; r++) s2 += vs[r][t - 64];
        }
        __syncthreads();
    }
    float* kvout = g_kv + (size_t)bh * 4096;
#pragma unroll
    for (int i = 0; i < 4; i++)
#pragma unroll
        for (int j = 0; j < 4; j++)
            kvout[(ty * 4 + i) * 64 + tx * 4 + j] = acc[i][j];
    if (t < 64) g_ksum[bh * 64 + t] = s1;
    else if (t < 128) g_vsum[bh * 64 + (t - 64)] = s2;
}

// ================= fused attention output: P=Q@KV, den, combine -> out ==========
// grid = (64, 16): b, 32-row chunk. All 4 heads in SMEM. 105KB -> 2 CTAs/SM.
#define QS_STRIDE 36
#define ATT_FLOATS (9216 + 16384 + 256 + 256 + 128)
#define ATT_SMEM (ATT_FLOATS * 4)
__global__ __launch_bounds__(256, 2) void att_kernel(const int* __restrict__ nnodes,
                                                     float* __restrict__ out) {
    extern __shared__ float sm[];
    float* Qs   = sm;                    // [h][k][m] stride QS_STRIDE
    float* KVs  = sm + 9216;             // [h][k*64+d]
    float* ksum = sm + 9216 + 16384;
    float* vsum = ksum + 256;
    float* dens = vsum + 256;            // [m][h], m in 0..31

    const int t = threadIdx.x;
    const int b = blockIdx.x, chunk = blockIdx.y;
    const int n0 = b * 512 + chunk * 32;

    // load Q (32 rows x 256 cols) transposed per head
    {
        const float* qb = g_q + (size_t)n0 * 256;
        int la_m = t >> 3;
        int cb0 = (t & 7) * 4;
#pragma unroll
        for (int j = 0; j < 8; j++) {
            int c = cb0 + j * 32;
            int h = c >> 6, kk = c & 63;
            float4 v4 = *(const float4*)(qb + (size_t)la_m * 256 + c);
            float* Qh = Qs + h * (64 * QS_STRIDE);
            Qh[(kk + 0) * QS_STRIDE + la_m] = v4.x;
            Qh[(kk + 1) * QS_STRIDE + la_m] = v4.y;
            Qh[(kk + 2) * QS_STRIDE + la_m] = v4.z;
            Qh[(kk + 3) * QS_STRIDE + la_m] = v4.w;
        }
    }
    {
        const float* kvb = g_kv + (size_t)b * 16384;
#pragma unroll
        for (int j = 0; j < 16; j++)
            *(float4*)&KVs[(t + j * 256) * 4] = *(const float4*)(kvb + (t + j * 256) * 4);
        ksum[t] = g_ksum[b * 256 + t];
        vsum[t] = g_vsum[b * 256 + t];
    }
    __syncthreads();

    if (t < 128) {
        int h = t >> 5, m = t & 31;
        const float* Qh = Qs + h * (64 * QS_STRIDE);
        const float* kh = ksum + h * 64;
        float p = 0.f;
#pragma unroll
        for (int k = 0; k < 64; k++) p = fmaf(Qh[k * QS_STRIDE + m], kh[k], p);
        dens[m * 4 + h] = p;
    }
    __syncthreads();

    const float s = rsqrtf(g_sumsq[0]) * rsqrtf(g_sumsq[1]);
    const float nnv = (float)nnodes[b];
    const int rm0 = (t >> 4) * 2, cn0 = (t & 15) * 4;

    float o[2][4];
#pragma unroll
    for (int i = 0; i < 2; i++)
#pragma unroll
        for (int j = 0; j < 4; j++) o[i][j] = 0.f;

#pragma unroll
    for (int h = 0; h < 4; h++) {
        const float* Qh = Qs + h * (64 * QS_STRIDE);
        const float* KVh = KVs + h * 4096;
        float acc[2][4] = {};
#pragma unroll
        for (int k = 0; k < 64; k++) {
            float2 qa = *(const float2*)&Qh[k * QS_STRIDE + rm0];
            float4 t1 = *(const float4*)&KVh[k * 64 + cn0];
            acc[0][0] = fmaf(qa.x, t1.x, acc[0][0]);
            acc[0][1] = fmaf(qa.x, t1.y, acc[0][1]);
            acc[0][2] = fmaf(qa.x, t1.z, acc[0][2]);
            acc[0][3] = fmaf(qa.x, t1.w, acc[0][3]);
            acc[1][0] = fmaf(qa.y, t1.x, acc[1][0]);
            acc[1][1] = fmaf(qa.y, t1.y, acc[1][1]);
            acc[1][2] = fmaf(qa.y, t1.z, acc[1][2]);
            acc[1][3] = fmaf(qa.y, t1.w, acc[1][3]);
        }
#pragma unroll
        for (int i = 0; i < 2; i++) {
            float inv = 1.0f / fmaf(s, dens[(rm0 + i) * 4 + h], nnv);
#pragma unroll
            for (int j = 0; j < 4; j++)
                o[i][j] += fmaf(s, acc[i][j], vsum[h * 64 + cn0 + j]) * inv;
        }
    }
#pragma unroll
    for (int i = 0; i < 2; i++)
        *(float4*)(out + (size_t)(n0 + rm0 + i) * 64 + cn0) =
            make_float4(0.25f * o[i][0], 0.25f * o[i][1], 0.25f * o[i][2], 0.25f * o[i][3]);
}

// ================= GCN scatter =================
__global__ void gcn_kernel(const int* __restrict__ ei, const float* __restrict__ ew,
                           float* __restrict__ out) {
    int gid = blockIdx.x * 256 + threadIdx.x;
    int e = gid >> 4, li = gid & 15;
    int row = ei[e];
    int col = ei[EE + e];
    float p = g_deg[col] * g_deg[row];
    float coeff = (p > 0.f) ? ew[e] * rsqrtf(p) : 0.f;
    float4 vv = *(const float4*)(g_vmean + (size_t)row * 64 + li * 4);
    float* dst = out + (size_t)col * 64 + li * 4;
    asm volatile("red.global.add.v4.f32 [%0], {%1,%2,%3,%4};"
                 :: "l"(dst), "f"(coeff * vv.x), "f"(coeff * vv.y),
                    "f"(coeff * vv.z), "f"(coeff * vv.w)
                 : "memory");
}

extern "C" void kernel_launch(void* const* d_in, const int* in_sizes, int n_in,
                              void* d_out, int out_size) {
    const float* Xq = (const float*)d_in[0];
    const float* Xs = (const float*)d_in[1];
    const float* ew = (const float*)d_in[2];
    const float* Wq = (const float*)d_in[3];
    const float* bq = (const float*)d_in[4];
    const float* Wk = (const float*)d_in[5];
    const float* bk = (const float*)d_in[6];
    const float* Wv = (const float*)d_in[7];
    const float* bv = (const float*)d_in[8];
    const int*   nn = (const int*)d_in[9];
    const int*   ei = (const int*)d_in[10];
    float* out = (float*)d_out;

    cudaFuncSetAttribute(att_kernel, cudaFuncAttributeMaxDynamicSharedMemorySize, ATT_SMEM);

    // order: proj is launch #3 (0-indexed) -> lands in the ncu capture window
    init_kernel<<<128, 256>>>();
    wconv_kernel<<<dim3(256, 3), 256>>>(Wq, Wk, Wv);
    deg_kernel<<<EE / 256, 256>>>(ei);
    proj_mma_kernel<<<dim3(2, 256, 3), 256>>>(Xq, Xs, bq, bk, bv);
    vmean_kernel<<<(NN * 64) / 256, 256>>>();
    kv_kernel<<<BB * NH, 256>>>();
    att_kernel<<<dim3(BB, 16), 256, ATT_SMEM>>>(nn, out);
    gcn_kernel<<<(EE * 16) / 256, 256>>>(ei, ew, out);
}

// round 9
// speedup vs baseline: 1.7538x; 1.1166x over previous
#include <cuda_runtime.h>
#include <cuda_fp16.h>
#include <stdint.h>

#define NN 32768      // B*M nodes
#define NH 4
#define DD 64
#define BB 64
#define MM 512
#define EE 524288

// ================= device scratch =================
static __device__ float g_q[NN * 256];
static __device__ float g_k[NN * 256];
static __device__ float g_v[NN * 256];
static __device__ float g_vmean[NN * DD];
static __device__ float g_kv[BB * NH * DD * DD];
static __device__ float g_ksum[BB * NH * DD];
static __device__ float g_vsum[BB * NH * DD];
static __device__ float g_deg[NN];
static __device__ float g_sumsq[2];
static __device__ __align__(16) __half g_wt[3 * 256 * 256];  // [w][n][k] = fp16(W[k][n])

// ================= init =================
__global__ void init_kernel() {
    int i = blockIdx.x * 256 + threadIdx.x;
    if (i < NN) g_deg[i] = 0.f;
    if (i < 2) g_sumsq[i] = 0.f;
}

// ================= W transpose -> fp16 =================
__global__ void wconv_kernel(const float* __restrict__ Wq, const float* __restrict__ Wk,
                             const float* __restrict__ Wv) {
    int w = blockIdx.y, n = blockIdx.x, k = threadIdx.x;
    const float* W = (w == 0) ? Wq : ((w == 1) ? Wk : Wv);
    g_wt[(w * 256 + n) * 256 + k] = __float2half_rn(W[k * 256 + n]);
}

// ================= mma.sync helpers (arch-generic PTX) =================
__device__ __forceinline__ uint32_t smem_u32(const void* p) {
    uint32_t a;
    asm("{ .reg .u64 t; cvta.to.shared.u64 t, %1; cvt.u32.u64 %0, t; }" : "=r"(a) : "l"(p));
    return a;
}
__device__ __forceinline__ void ldmx4(uint32_t* r, uint32_t addr) {
    asm volatile("ldmatrix.sync.aligned.m8n8.x4.shared.b16 {%0,%1,%2,%3}, [%4];"
                 : "=r"(r[0]), "=r"(r[1]), "=r"(r[2]), "=r"(r[3]) : "r"(addr));
}
__device__ __forceinline__ void mma16816(float* d, const uint32_t* a, const uint32_t* b) {
    asm volatile(
        "mma.sync.aligned.m16n8k16.row.col.f32.f16.f16.f32 "
        "{%0,%1,%2,%3}, {%4,%5,%6,%7}, {%8,%9}, {%0,%1,%2,%3};"
        : "+f"(d[0]), "+f"(d[1]), "+f"(d[2]), "+f"(d[3])
        : "r"(a[0]), "r"(a[1]), "r"(a[2]), "r"(a[3]), "r"(b[0]), "r"(b[1]));
}

// ================= projection GEMM via tensor cores (fp16 single-product) ========
// D = fp16(A) * fp16(W).  grid (2, 256, 3), CTA tile 128x128, BK=32, 8 warps (2x4).
#define SROW 40
__global__ __launch_bounds__(256, 2) void proj_mma_kernel(
    const float* __restrict__ Xq, const float* __restrict__ Xs,
    const float* __restrict__ bq, const float* __restrict__ bk,
    const float* __restrict__ bv)
{
    __shared__ __half Ah[128 * SROW];
    __shared__ __half Bh[128 * SROW];

    const int t = threadIdx.x, lane = t & 31, wid = t >> 5;
    const int wm = wid >> 2, wn = wid & 3;          // 2 x 4 warp grid
    const int y = blockIdx.z;
    const float* A    = (y == 0) ? Xq : Xs;
    const float* bias = (y == 0) ? bq : ((y == 1) ? bk : bv);
    float* C          = (y == 0) ? g_q : ((y == 1) ? g_k : g_v);
    const int sqidx   = (y == 2) ? -1 : y;
    const int row0 = blockIdx.y * 128;
    const int col0 = blockIdx.x * 128;

    const __half* Wt = g_wt + y * 65536;

    const uint32_t ah_b = smem_u32(Ah);
    const uint32_t bh_b = smem_u32(Bh);

    const uint32_t a_lrow = lane & 15, a_lcol = (lane >> 4) * 8;
    const uint32_t b_lrow = lane & 7, b_lcol = (lane >> 3) * 8;

    float acc[4][4][4];
#pragma unroll
    for (int i = 0; i < 4; i++)
#pragma unroll
        for (int j = 0; j < 4; j++)
#pragma unroll
            for (int r = 0; r < 4; r++) acc[i][j][r] = 0.f;

    const int ar = t >> 1, ac = (t & 1);       // A loader: 2 threads/row
    const int br2 = t >> 1, bq2 = t & 1;       // B loader

    for (int kt = 0; kt < 8; kt++) {
        const int k0 = kt * 32;
        __syncthreads();
        // ---- A chunk: fp32 -> fp16 ----
#pragma unroll
        for (int i = 0; i < 4; i++) {
            int cf = ac * 4 + i;               // float4 index 0..7
            float4 a4 = *(const float4*)(A + (size_t)(row0 + ar) * 256 + k0 + cf * 4);
            __half2 p0 = __floats2half2_rn(a4.x, a4.y);
            __half2 p1 = __floats2half2_rn(a4.z, a4.w);
            int o = ar * SROW + cf * 4;
            *(uint2*)&Ah[o] = make_uint2(*(uint32_t*)&p0, *(uint32_t*)&p1);
        }
        // ---- B chunk (fp16 W^T rows) ----
#pragma unroll
        for (int j = 0; j < 2; j++) {
            int u = bq2 * 2 + j;               // uint4 index 0..3 (8 halfs each)
            const char* src = (const char*)(Wt + (size_t)(col0 + br2) * 256 + k0) + u * 16;
            int o = br2 * SROW + u * 8;
            *(uint4*)&Bh[o] = *(const uint4*)src;
        }
        __syncthreads();

        // ---- preload B fragments (both k-halves) ----
        uint32_t bhf[4][4];
#pragma unroll
        for (int nf = 0; nf < 4; nf++) {
            uint32_t n = wn * 32 + nf * 8 + b_lrow;
            uint32_t off = (n * SROW + b_lcol) * 2;
            ldmx4(bhf[nf], bh_b + off);
        }
        // ---- mma: 1 product per fragment ----
#pragma unroll
        for (int kf = 0; kf < 2; kf++) {
#pragma unroll
            for (int mf = 0; mf < 4; mf++) {
                uint32_t row = wm * 64 + mf * 16 + a_lrow;
                uint32_t off = (row * SROW + kf * 16 + a_lcol) * 2;
                uint32_t ahf[4];
                ldmx4(ahf, ah_b + off);
#pragma unroll
                for (int nf = 0; nf < 4; nf++)
                    mma16816(acc[mf][nf], ahf, &bhf[nf][kf * 2]);
            }
        }
    }

    // ---- epilogue: bias + store + global sumsq ----
    float ss = 0.f;
    const int rql = lane >> 2, cql = (lane & 3) * 2;
#pragma unroll
    for (int mf = 0; mf < 4; mf++) {
        int r0 = row0 + wm * 64 + mf * 16 + rql;
#pragma unroll
        for (int nf = 0; nf < 4; nf++) {
            int c = col0 + wn * 32 + nf * 8 + cql;
            float b0 = bias[c], b1 = bias[c + 1];
            float v0 = acc[mf][nf][0] + b0, v1 = acc[mf][nf][1] + b1;
            float v2 = acc[mf][nf][2] + b0, v3 = acc[mf][nf][3] + b1;
            ss += v0 * v0 + v1 * v1 + v2 * v2 + v3 * v3;
            *(float2*)(C + (size_t)r0 * 256 + c)       = make_float2(v0, v1);
            *(float2*)(C + (size_t)(r0 + 8) * 256 + c) = make_float2(v2, v3);
        }
    }
    if (sqidx >= 0) {
#pragma unroll
        for (int o = 16; o > 0; o >>= 1) ss += __shfl_down_sync(0xffffffffu, ss, o);
        if (lane == 0) atomicAdd(&g_sumsq[sqidx], ss);
    }
}

// ================= degree =================
__global__ void deg_kernel(const int* __restrict__ ei) {
    int e = blockIdx.x * 256 + threadIdx.x;
    if (e < EE) atomicAdd(&g_deg[ei[EE + e]], 1.0f);
}

// ================= head-mean of v =================
__global__ void vmean_kernel() {
    int i = blockIdx.x * 256 + threadIdx.x;
    int n = i >> 6, d = i & 63;
    const float* vr = g_v + (size_t)n * 256 + d;
    g_vmean[i] = 0.25f * (vr[0] + vr[64] + vr[128] + vr[192]);
}

// ================= per (b,h): kv, ksum, vsum =================
__global__ __launch_bounds__(256) void kv_kernel() {
    int bh = blockIdx.x;
    int b = bh >> 2, h = bh & 3;
    __shared__ float ks[8][64], vs[8][64];
    int t = threadIdx.x;
    int ty = t >> 4, tx = t & 15;
    float acc[4][4] = {};
    float s1 = 0.f, s2 = 0.f;
    const float* kb = g_k + (size_t)b * 512 * 256 + h * 64;
    const float* vb = g_v + (size_t)b * 512 * 256 + h * 64;

    for (int m0 = 0; m0 < 512; m0 += 8) {
#pragma unroll
        for (int j = 0; j < 2; j++) {
            int i = t + j * 256;
            int r = i >> 6, c2 = i & 63;
            ks[r][c2] = kb[(size_t)(m0 + r) * 256 + c2];
            vs[r][c2] = vb[(size_t)(m0 + r) * 256 + c2];
        }
        __syncthreads();
#pragma unroll
        for (int r = 0; r < 8; r++) {
            float kr[4], vr[4];
            float4 k4 = *(const float4*)&ks[r][ty * 4];
            float4 v4 = *(const float4*)&vs[r][tx * 4];
            kr[0]=k4.x; kr[1]=k4.y; kr[2]=k4.z; kr[3]=k4.w;
            vr[0]=v4.x; vr[1]=v4.y; vr[2]=v4.z; vr[3]=v4.w;
#pragma unroll
            for (int i = 0; i < 4; i++)
#pragma unroll
                for (int j = 0; j < 4; j++)
                    acc[i][j] = fmaf(kr[i], vr[j], acc[i][j]);
        }
        if (t < 64) {
#pragma unroll
            for (int r = 0; r < 8; r++) s1 += ks[r][t];
        } else if (t < 128) {
#pragma unroll
            for (int r = 0; r < 8; r++) s2 += vs[r][t - 64];
        }
        __syncthreads();
    }
    float* kvout = g_kv + (size_t)bh * 4096;
#pragma unroll
    for (int i = 0; i < 4; i++)
#pragma unroll
        for (int j = 0; j < 4; j++)
            kvout[(ty * 4 + i) * 64 + tx * 4 + j] = acc[i][j];
    if (t < 64) g_ksum[bh * 64 + t] = s1;
    else if (t < 128) g_vsum[bh * 64 + (t - 64)] = s2;
}

// ================= fused attention output: P=Q@KV, den, combine -> out ==========
// grid = (64, 16): b, 32-row chunk. All 4 heads in SMEM. 105KB -> 2 CTAs/SM.
#define QS_STRIDE 36
#define ATT_FLOATS (9216 + 16384 + 256 + 256 + 128)
#define ATT_SMEM (ATT_FLOATS * 4)
__global__ __launch_bounds__(256, 2) void att_kernel(const int* __restrict__ nnodes,
                                                     float* __restrict__ out) {
    extern __shared__ float sm[];
    float* Qs   = sm;                    // [h][k][m] stride QS_STRIDE
    float* KVs  = sm + 9216;             // [h][k*64+d]
    float* ksum = sm + 9216 + 16384;
    float* vsum = ksum + 256;
    float* dens = vsum + 256;            // [m][h], m in 0..31

    const int t = threadIdx.x;
    const int b = blockIdx.x, chunk = blockIdx.y;
    const int n0 = b * 512 + chunk * 32;

    // load Q (32 rows x 256 cols) transposed per head
    {
        const float* qb = g_q + (size_t)n0 * 256;
        int la_m = t >> 3;
        int cb0 = (t & 7) * 4;
#pragma unroll
        for (int j = 0; j < 8; j++) {
            int c = cb0 + j * 32;
            int h = c >> 6, kk = c & 63;
            float4 v4 = *(const float4*)(qb + (size_t)la_m * 256 + c);
            float* Qh = Qs + h * (64 * QS_STRIDE);
            Qh[(kk + 0) * QS_STRIDE + la_m] = v4.x;
            Qh[(kk + 1) * QS_STRIDE + la_m] = v4.y;
            Qh[(kk + 2) * QS_STRIDE + la_m] = v4.z;
            Qh[(kk + 3) * QS_STRIDE + la_m] = v4.w;
        }
    }
    {
        const float* kvb = g_kv + (size_t)b * 16384;
#pragma unroll
        for (int j = 0; j < 16; j++)
            *(float4*)&KVs[(t + j * 256) * 4] = *(const float4*)(kvb + (t + j * 256) * 4);
        ksum[t] = g_ksum[b * 256 + t];
        vsum[t] = g_vsum[b * 256 + t];
    }
    __syncthreads();

    if (t < 128) {
        int h = t >> 5, m = t & 31;
        const float* Qh = Qs + h * (64 * QS_STRIDE);
        const float* kh = ksum + h * 64;
        float p = 0.f;
#pragma unroll
        for (int k = 0; k < 64; k++) p = fmaf(Qh[k * QS_STRIDE + m], kh[k], p);
        dens[m * 4 + h] = p;
    }
    __syncthreads();

    const float s = rsqrtf(g_sumsq[0]) * rsqrtf(g_sumsq[1]);
    const float nnv = (float)nnodes[b];
    const int rm0 = (t >> 4) * 2, cn0 = (t & 15) * 4;

    float o[2][4];
#pragma unroll
    for (int i = 0; i < 2; i++)
#pragma unroll
        for (int j = 0; j < 4; j++) o[i][j] = 0.f;

#pragma unroll
    for (int h = 0; h < 4; h++) {
        const float* Qh = Qs + h * (64 * QS_STRIDE);
        const float* KVh = KVs + h * 4096;
        float acc[2][4] = {};
#pragma unroll
        for (int k = 0; k < 64; k++) {
            float2 qa = *(const float2*)&Qh[k * QS_STRIDE + rm0];
            float4 t1 = *(const float4*)&KVh[k * 64 + cn0];
            acc[0][0] = fmaf(qa.x, t1.x, acc[0][0]);
            acc[0][1] = fmaf(qa.x, t1.y, acc[0][1]);
            acc[0][2] = fmaf(qa.x, t1.z, acc[0][2]);
            acc[0][3] = fmaf(qa.x, t1.w, acc[0][3]);
            acc[1][0] = fmaf(qa.y, t1.x, acc[1][0]);
            acc[1][1] = fmaf(qa.y, t1.y, acc[1][1]);
            acc[1][2] = fmaf(qa.y, t1.z, acc[1][2]);
            acc[1][3] = fmaf(qa.y, t1.w, acc[1][3]);
        }
#pragma unroll
        for (int i = 0; i < 2; i++) {
            float inv = 1.0f / fmaf(s, dens[(rm0 + i) * 4 + h], nnv);
#pragma unroll
            for (int j = 0; j < 4; j++)
                o[i][j] += fmaf(s, acc[i][j], vsum[h * 64 + cn0 + j]) * inv;
        }
    }
#pragma unroll
    for (int i = 0; i < 2; i++)
        *(float4*)(out + (size_t)(n0 + rm0 + i) * 64 + cn0) =
            make_float4(0.25f * o[i][0], 0.25f * o[i][1], 0.25f * o[i][2], 0.25f * o[i][3]);
}

// ================= GCN scatter =================
__global__ void gcn_kernel(const int* __restrict__ ei, const float* __restrict__ ew,
                           float* __restrict__ out) {
    int gid = blockIdx.x * 256 + threadIdx.x;
    int e = gid >> 4, li = gid & 15;
    int row = ei[e];
    int col = ei[EE + e];
    float p = g_deg[col] * g_deg[row];
    float coeff = (p > 0.f) ? ew[e] * rsqrtf(p) : 0.f;
    float4 vv = *(const float4*)(g_vmean + (size_t)row * 64 + li * 4);
    float* dst = out + (size_t)col * 64 + li * 4;
    asm volatile("red.global.add.v4.f32 [%0], {%1,%2,%3,%4};"
                 :: "l"(dst), "f"(coeff * vv.x), "f"(coeff * vv.y),
                    "f"(coeff * vv.z), "f"(coeff * vv.w)
                 : "memory");
}

extern "C" void kernel_launch(void* const* d_in, const int* in_sizes, int n_in,
                              void* d_out, int out_size) {
    const float* Xq = (const float*)d_in[0];
    const float* Xs = (const float*)d_in[1];
    const float* ew = (const float*)d_in[2];
    const float* Wq = (const float*)d_in[3];
    const float* bq = (const float*)d_in[4];
    const float* Wk = (const float*)d_in[5];
    const float* bk = (const float*)d_in[6];
    const float* Wv = (const float*)d_in[7];
    const float* bv = (const float*)d_in[8];
    const int*   nn = (const int*)d_in[9];
    const int*   ei = (const int*)d_in[10];
    float* out = (float*)d_out;

    cudaFuncSetAttribute(att_kernel, cudaFuncAttributeMaxDynamicSharedMemorySize, ATT_SMEM);

    // order keeps proj in the ncu capture window (launch index 3)
    init_kernel<<<128, 256>>>();
    wconv_kernel<<<dim3(256, 3), 256>>>(Wq, Wk, Wv);
    deg_kernel<<<EE / 256, 256>>>(ei);
    proj_mma_kernel<<<dim3(2, 256, 3), 256>>>(Xq, Xs, bq, bk, bv);
    vmean_kernel<<<(NN * 64) / 256, 256>>>();
    kv_kernel<<<BB * NH, 256>>>();
    att_kernel<<<dim3(BB, 16), 256, ATT_SMEM>>>(nn, out);
    gcn_kernel<<<(EE * 16) / 256, 256>>>(ei, ew, out);
}

// round 10
// speedup vs baseline: 1.9323x; 1.1018x over previous
#include <cuda_runtime.h>
#include <cuda_fp16.h>
#include <stdint.h>

#define NN 32768      // B*M nodes
#define NH 4
#define DD 64
#define BB 64
#define MM 512
#define EE 524288

// ================= device scratch =================
static __device__ float g_q[NN * 256];
static __device__ float g_k[NN * 256];
static __device__ float g_v[NN * 256];
static __device__ __half g_vmeanh[NN * DD];
static __device__ float g_kv[BB * NH * DD * DD];
static __device__ float g_ksum[BB * NH * DD];
static __device__ float g_vsum[BB * NH * DD];
static __device__ float g_deg[NN];
static __device__ float g_sumsq[2];
static __device__ __align__(16) __half g_wt[3 * 256 * 256];  // [w][n][k] = fp16(W[k][n])

// ================= init: zero all accumulators =================
// zero range: g_kv (1048576) | g_ksum (16384) | g_vsum (16384) | g_deg (32768) | g_sumsq (2)
#define ZTOT (1048576 + 16384 + 16384 + 32768 + 2)
__global__ void init_kernel() {
    int i = blockIdx.x * 256 + threadIdx.x;
    if (i < 1048576) { g_kv[i] = 0.f; return; }
    i -= 1048576;
    if (i < 16384) { g_ksum[i] = 0.f; return; }
    i -= 16384;
    if (i < 16384) { g_vsum[i] = 0.f; return; }
    i -= 16384;
    if (i < 32768) { g_deg[i] = 0.f; return; }
    i -= 32768;
    if (i < 2) g_sumsq[i] = 0.f;
}

// ================= W transpose -> fp16 =================
__global__ void wconv_kernel(const float* __restrict__ Wq, const float* __restrict__ Wk,
                             const float* __restrict__ Wv) {
    int w = blockIdx.y, n = blockIdx.x, k = threadIdx.x;
    const float* W = (w == 0) ? Wq : ((w == 1) ? Wk : Wv);
    g_wt[(w * 256 + n) * 256 + k] = __float2half_rn(W[k * 256 + n]);
}

// ================= mma.sync helpers (arch-generic PTX) =================
__device__ __forceinline__ uint32_t smem_u32(const void* p) {
    uint32_t a;
    asm("{ .reg .u64 t; cvta.to.shared.u64 t, %1; cvt.u32.u64 %0, t; }" : "=r"(a) : "l"(p));
    return a;
}
__device__ __forceinline__ void ldmx4(uint32_t* r, uint32_t addr) {
    asm volatile("ldmatrix.sync.aligned.m8n8.x4.shared.b16 {%0,%1,%2,%3}, [%4];"
                 : "=r"(r[0]), "=r"(r[1]), "=r"(r[2]), "=r"(r[3]) : "r"(addr));
}
__device__ __forceinline__ void mma16816(float* d, const uint32_t* a, const uint32_t* b) {
    asm volatile(
        "mma.sync.aligned.m16n8k16.row.col.f32.f16.f16.f32 "
        "{%0,%1,%2,%3}, {%4,%5,%6,%7}, {%8,%9}, {%0,%1,%2,%3};"
        : "+f"(d[0]), "+f"(d[1]), "+f"(d[2]), "+f"(d[3])
        : "r"(a[0]), "r"(a[1]), "r"(a[2]), "r"(a[3]), "r"(b[0]), "r"(b[1]));
}
__device__ __forceinline__ void redg4(float* p, float a, float b, float c, float d) {
    asm volatile("red.global.add.v4.f32 [%0], {%1,%2,%3,%4};"
                 :: "l"(p), "f"(a), "f"(b), "f"(c), "f"(d) : "memory");
}
__device__ __forceinline__ void redg1(float* p, float a) {
    asm volatile("red.global.add.f32 [%0], %1;" :: "l"(p), "f"(a) : "memory");
}

// ================= projection GEMM via tensor cores (fp16 single-product) ========
#define SROW 40
__global__ __launch_bounds__(256, 2) void proj_mma_kernel(
    const float* __restrict__ Xq, const float* __restrict__ Xs,
    const float* __restrict__ bq, const float* __restrict__ bk,
    const float* __restrict__ bv)
{
    __shared__ __half Ah[128 * SROW];
    __shared__ __half Bh[128 * SROW];

    const int t = threadIdx.x, lane = t & 31, wid = t >> 5;
    const int wm = wid >> 2, wn = wid & 3;          // 2 x 4 warp grid
    const int y = blockIdx.z;
    const float* A    = (y == 0) ? Xq : Xs;
    const float* bias = (y == 0) ? bq : ((y == 1) ? bk : bv);
    float* C          = (y == 0) ? g_q : ((y == 1) ? g_k : g_v);
    const int sqidx   = (y == 2) ? -1 : y;
    const int row0 = blockIdx.y * 128;
    const int col0 = blockIdx.x * 128;

    const __half* Wt = g_wt + y * 65536;

    const uint32_t ah_b = smem_u32(Ah);
    const uint32_t bh_b = smem_u32(Bh);

    const uint32_t a_lrow = lane & 15, a_lcol = (lane >> 4) * 8;
    const uint32_t b_lrow = lane & 7, b_lcol = (lane >> 3) * 8;

    float acc[4][4][4];
#pragma unroll
    for (int i = 0; i < 4; i++)
#pragma unroll
        for (int j = 0; j < 4; j++)
#pragma unroll
            for (int r = 0; r < 4; r++) acc[i][j][r] = 0.f;

    const int ar = t >> 1, ac = (t & 1);
    const int br2 = t >> 1, bq2 = t & 1;

    for (int kt = 0; kt < 8; kt++) {
        const int k0 = kt * 32;
        __syncthreads();
#pragma unroll
        for (int i = 0; i < 4; i++) {
            int cf = ac * 4 + i;
            float4 a4 = *(const float4*)(A + (size_t)(row0 + ar) * 256 + k0 + cf * 4);
            __half2 p0 = __floats2half2_rn(a4.x, a4.y);
            __half2 p1 = __floats2half2_rn(a4.z, a4.w);
            int o = ar * SROW + cf * 4;
            *(uint2*)&Ah[o] = make_uint2(*(uint32_t*)&p0, *(uint32_t*)&p1);
        }
#pragma unroll
        for (int j = 0; j < 2; j++) {
            int u = bq2 * 2 + j;
            const char* src = (const char*)(Wt + (size_t)(col0 + br2) * 256 + k0) + u * 16;
            int o = br2 * SROW + u * 8;
            *(uint4*)&Bh[o] = *(const uint4*)src;
        }
        __syncthreads();

        uint32_t bhf[4][4];
#pragma unroll
        for (int nf = 0; nf < 4; nf++) {
            uint32_t n = wn * 32 + nf * 8 + b_lrow;
            uint32_t off = (n * SROW + b_lcol) * 2;
            ldmx4(bhf[nf], bh_b + off);
        }
#pragma unroll
        for (int kf = 0; kf < 2; kf++) {
#pragma unroll
            for (int mf = 0; mf < 4; mf++) {
                uint32_t row = wm * 64 + mf * 16 + a_lrow;
                uint32_t off = (row * SROW + kf * 16 + a_lcol) * 2;
                uint32_t ahf[4];
                ldmx4(ahf, ah_b + off);
#pragma unroll
                for (int nf = 0; nf < 4; nf++)
                    mma16816(acc[mf][nf], ahf, &bhf[nf][kf * 2]);
            }
        }
    }

    float ss = 0.f;
    const int rql = lane >> 2, cql = (lane & 3) * 2;
#pragma unroll
    for (int mf = 0; mf < 4; mf++) {
        int r0 = row0 + wm * 64 + mf * 16 + rql;
#pragma unroll
        for (int nf = 0; nf < 4; nf++) {
            int c = col0 + wn * 32 + nf * 8 + cql;
            float b0 = bias[c], b1 = bias[c + 1];
            float v0 = acc[mf][nf][0] + b0, v1 = acc[mf][nf][1] + b1;
            float v2 = acc[mf][nf][2] + b0, v3 = acc[mf][nf][3] + b1;
            ss += v0 * v0 + v1 * v1 + v2 * v2 + v3 * v3;
            *(float2*)(C + (size_t)r0 * 256 + c)       = make_float2(v0, v1);
            *(float2*)(C + (size_t)(r0 + 8) * 256 + c) = make_float2(v2, v3);
        }
    }
    if (sqidx >= 0) {
#pragma unroll
        for (int o = 16; o > 0; o >>= 1) ss += __shfl_down_sync(0xffffffffu, ss, o);
        if (lane == 0) atomicAdd(&g_sumsq[sqidx], ss);
    }
}

// ================= degree =================
__global__ void deg_kernel(const int* __restrict__ ei) {
    int e = blockIdx.x * 256 + threadIdx.x;
    if (e < EE) atomicAdd(&g_deg[ei[EE + e]], 1.0f);
}

// ================= head-mean of v -> fp16 =================
__global__ void vmean_kernel() {
    int i = blockIdx.x * 256 + threadIdx.x;    // NN*32 threads
    int n = i >> 5, dp = (i & 31) * 2;
    const float* vr = g_v + (size_t)n * 256 + dp;
    float2 a0 = *(const float2*)(vr);
    float2 a1 = *(const float2*)(vr + 64);
    float2 a2 = *(const float2*)(vr + 128);
    float2 a3 = *(const float2*)(vr + 192);
    float x = 0.25f * (a0.x + a1.x + a2.x + a3.x);
    float y = 0.25f * (a0.y + a1.y + a2.y + a3.y);
    *(__half2*)(g_vmeanh + (size_t)n * 64 + dp) = __floats2half2_rn(x, y);
}

// ================= per (b,h,mchunk): kv, ksum, vsum partials via red.global =====
// grid = (256, 4): bh, m-chunk of 128.
__global__ __launch_bounds__(256) void kv_kernel() {
    int bh = blockIdx.x, mc = blockIdx.y;
    int b = bh >> 2, h = bh & 3;
    __shared__ float ks[8][64], vs[8][64];
    int t = threadIdx.x;
    int ty = t >> 4, tx = t & 15;
    float acc[4][4] = {};
    float s1 = 0.f, s2 = 0.f;
    const float* kb = g_k + (size_t)b * 512 * 256 + (size_t)mc * 128 * 256 + h * 64;
    const float* vb = g_v + (size_t)b * 512 * 256 + (size_t)mc * 128 * 256 + h * 64;

    for (int m0 = 0; m0 < 128; m0 += 8) {
#pragma unroll
        for (int j = 0; j < 2; j++) {
            int i = t + j * 256;
            int r = i >> 6, c2 = i & 63;
            ks[r][c2] = kb[(size_t)(m0 + r) * 256 + c2];
            vs[r][c2] = vb[(size_t)(m0 + r) * 256 + c2];
        }
        __syncthreads();
#pragma unroll
        for (int r = 0; r < 8; r++) {
            float kr[4], vr[4];
            float4 k4 = *(const float4*)&ks[r][ty * 4];
            float4 v4 = *(const float4*)&vs[r][tx * 4];
            kr[0]=k4.x; kr[1]=k4.y; kr[2]=k4.z; kr[3]=k4.w;
            vr[0]=v4.x; vr[1]=v4.y; vr[2]=v4.z; vr[3]=v4.w;
#pragma unroll
            for (int i = 0; i < 4; i++)
#pragma unroll
                for (int j = 0; j < 4; j++)
                    acc[i][j] = fmaf(kr[i], vr[j], acc[i][j]);
        }
        if (t < 64) {
#pragma unroll
            for (int r = 0; r < 8; r++) s1 += ks[r][t];
        } else if (t < 128) {
#pragma unroll
            for (int r = 0; r < 8; r++) s2 += vs[r][t - 64];
        }
        __syncthreads();
    }
    float* kvout = g_kv + (size_t)bh * 4096;
#pragma unroll
    for (int i = 0; i < 4; i++)
        redg4(kvout + (ty * 4 + i) * 64 + tx * 4, acc[i][0], acc[i][1], acc[i][2], acc[i][3]);
    if (t < 64) redg1(g_ksum + bh * 64 + t, s1);
    else if (t < 128) redg1(g_vsum + bh * 64 + (t - 64), s2);
}

// ================= fused attention output: P=Q@KV, den, combine -> out ==========
#define QS_STRIDE 36
#define ATT_FLOATS (9216 + 16384 + 256 + 256 + 128)
#define ATT_SMEM (ATT_FLOATS * 4)
__global__ __launch_bounds__(256, 2) void att_kernel(const int* __restrict__ nnodes,
                                                     float* __restrict__ out) {
    extern __shared__ float sm[];
    float* Qs   = sm;                    // [h][k][m] stride QS_STRIDE
    float* KVs  = sm + 9216;             // [h][k*64+d]
    float* ksum = sm + 9216 + 16384;
    float* vsum = ksum + 256;
    float* dens = vsum + 256;            // [m][h], m in 0..31

    const int t = threadIdx.x;
    const int b = blockIdx.x, chunk = blockIdx.y;
    const int n0 = b * 512 + chunk * 32;

    {
        const float* qb = g_q + (size_t)n0 * 256;
        int la_m = t >> 3;
        int cb0 = (t & 7) * 4;
#pragma unroll
        for (int j = 0; j < 8; j++) {
            int c = cb0 + j * 32;
            int h = c >> 6, kk = c & 63;
            float4 v4 = *(const float4*)(qb + (size_t)la_m * 256 + c);
            float* Qh = Qs + h * (64 * QS_STRIDE);
            Qh[(kk + 0) * QS_STRIDE + la_m] = v4.x;
            Qh[(kk + 1) * QS_STRIDE + la_m] = v4.y;
            Qh[(kk + 2) * QS_STRIDE + la_m] = v4.z;
            Qh[(kk + 3) * QS_STRIDE + la_m] = v4.w;
        }
    }
    {
        const float* kvb = g_kv + (size_t)b * 16384;
#pragma unroll
        for (int j = 0; j < 16; j++)
            *(float4*)&KVs[(t + j * 256) * 4] = *(const float4*)(kvb + (t + j * 256) * 4);
        ksum[t] = g_ksum[b * 256 + t];
        vsum[t] = g_vsum[b * 256 + t];
    }
    __syncthreads();

    if (t < 128) {
        int h = t >> 5, m = t & 31;
        const float* Qh = Qs + h * (64 * QS_STRIDE);
        const float* kh = ksum + h * 64;
        float p = 0.f;
#pragma unroll
        for (int k = 0; k < 64; k++) p = fmaf(Qh[k * QS_STRIDE + m], kh[k], p);
        dens[m * 4 + h] = p;
    }
    __syncthreads();

    const float s = rsqrtf(g_sumsq[0]) * rsqrtf(g_sumsq[1]);
    const float nnv = (float)nnodes[b];
    const int rm0 = (t >> 4) * 2, cn0 = (t & 15) * 4;

    float o[2][4];
#pragma unroll
    for (int i = 0; i < 2; i++)
#pragma unroll
        for (int j = 0; j < 4; j++) o[i][j] = 0.f;

#pragma unroll
    for (int h = 0; h < 4; h++) {
        const float* Qh = Qs + h * (64 * QS_STRIDE);
        const float* KVh = KVs + h * 4096;
        float acc[2][4] = {};
#pragma unroll
        for (int k = 0; k < 64; k++) {
            float2 qa = *(const float2*)&Qh[k * QS_STRIDE + rm0];
            float4 t1 = *(const float4*)&KVh[k * 64 + cn0];
            acc[0][0] = fmaf(qa.x, t1.x, acc[0][0]);
            acc[0][1] = fmaf(qa.x, t1.y, acc[0][1]);
            acc[0][2] = fmaf(qa.x, t1.z, acc[0][2]);
            acc[0][3] = fmaf(qa.x, t1.w, acc[0][3]);
            acc[1][0] = fmaf(qa.y, t1.x, acc[1][0]);
            acc[1][1] = fmaf(qa.y, t1.y, acc[1][1]);
            acc[1][2] = fmaf(qa.y, t1.z, acc[1][2]);
            acc[1][3] = fmaf(qa.y, t1.w, acc[1][3]);
        }
#pragma unroll
        for (int i = 0; i < 2; i++) {
            float inv = 1.0f / fmaf(s, dens[(rm0 + i) * 4 + h], nnv);
#pragma unroll
            for (int j = 0; j < 4; j++)
                o[i][j] += fmaf(s, acc[i][j], vsum[h * 64 + cn0 + j]) * inv;
        }
    }
#pragma unroll
    for (int i = 0; i < 2; i++)
        *(float4*)(out + (size_t)(n0 + rm0 + i) * 64 + cn0) =
            make_float4(0.25f * o[i][0], 0.25f * o[i][1], 0.25f * o[i][2], 0.25f * o[i][3]);
}

// ================= GCN scatter (fp16 vmean gather) =================
__global__ void gcn_kernel(const int* __restrict__ ei, const float* __restrict__ ew,
                           float* __restrict__ out) {
    int gid = blockIdx.x * 256 + threadIdx.x;  // EE*16 threads, 16 per edge
    int e = gid >> 4, li = gid & 15;
    int row = ei[e];
    int col = ei[EE + e];
    float p = g_deg[col] * g_deg[row];
    float coeff = (p > 0.f) ? ew[e] * rsqrtf(p) : 0.f;
    uint2 hv = *(const uint2*)(g_vmeanh + (size_t)row * 64 + li * 4);
    float2 f01 = __half22float2(*(__half2*)&hv.x);
    float2 f23 = __half22float2(*(__half2*)&hv.y);
    float* dst = out + (size_t)col * 64 + li * 4;
    redg4(dst, coeff * f01.x, coeff * f01.y, coeff * f23.x, coeff * f23.y);
}

extern "C" void kernel_launch(void* const* d_in, const int* in_sizes, int n_in,
                              void* d_out, int out_size) {
    const float* Xq = (const float*)d_in[0];
    const float* Xs = (const float*)d_in[1];
    const float* ew = (const float*)d_in[2];
    const float* Wq = (const float*)d_in[3];
    const float* bq = (const float*)d_in[4];
    const float* Wk = (const float*)d_in[5];
    const float* bk = (const float*)d_in[6];
    const float* Wv = (const float*)d_in[7];
    const float* bv = (const float*)d_in[8];
    const int*   nn = (const int*)d_in[9];
    const int*   ei = (const int*)d_in[10];
    float* out = (float*)d_out;

    cudaFuncSetAttribute(att_kernel, cudaFuncAttributeMaxDynamicSharedMemorySize, ATT_SMEM);

    // order keeps proj in the ncu capture window (launch index 3)
    init_kernel<<<(ZTOT + 255) / 256, 256>>>();
    wconv_kernel<<<dim3(256, 3), 256>>>(Wq, Wk, Wv);
    deg_kernel<<<EE / 256, 256>>>(ei);
    proj_mma_kernel<<<dim3(2, 256, 3), 256>>>(Xq, Xs, bq, bk, bv);
    vmean_kernel<<<(NN * 32) / 256, 256>>>();
    kv_kernel<<<dim3(BB * NH, 4), 256>>>();
    att_kernel<<<dim3(BB, 16), 256, ATT_SMEM>>>(nn, out);
    gcn_kernel<<<(EE * 16) / 256, 256>>>(ei, ew, out);
}